// round 6
// baseline (speedup 1.0000x reference)
#include <cuda_runtime.h>

#define HPF 32
#define NBLK 20
#define HID 640
#define BATCHN 128
#define SEQ 512
#define INSZ 16
#define NCTA 1280          // 20 j-blocks * 64 batch-pairs (1 warp per CTA, NB=2)

// ---- packed fp32x2 helpers (sm_103a dual fp32) ----
__device__ __forceinline__ unsigned long long pk2(float a, float b) {
    unsigned long long r;
    asm("mov.b64 %0, {%1, %2};" : "=l"(r) : "f"(a), "f"(b));
    return r;
}
__device__ __forceinline__ float2 upk2(unsigned long long v) {
    float2 f;
    asm("mov.b64 {%0, %1}, %2;" : "=f"(f.x), "=f"(f.y) : "l"(v));
    return f;
}
__device__ __forceinline__ void fma2(unsigned long long& d,
                                     unsigned long long a, unsigned long long b) {
    asm("fma.rn.f32x2 %0, %1, %2, %0;" : "+l"(d) : "l"(a), "l"(b));
}
__device__ __forceinline__ unsigned long long add2(unsigned long long a, unsigned long long b) {
    unsigned long long r;
    asm("add.rn.f32x2 %0, %1, %2;" : "=l"(r) : "l"(a), "l"(b));
    return r;
}
__device__ __forceinline__ float tanhapx(float x) {
    float r;
    asm("tanh.approx.f32 %0, %1;" : "=f"(r) : "f"(x));
    return r;
}

__global__ __launch_bounds__(32, 9)
void lstm_fused_kernel(const float* __restrict__ x,
                       const float* __restrict__ Ui, const float* __restrict__ Vi, const float* __restrict__ bi,
                       const float* __restrict__ Uf, const float* __restrict__ Vf, const float* __restrict__ bf,
                       const float* __restrict__ Uc, const float* __restrict__ Vc, const float* __restrict__ bc,
                       const float* __restrict__ Uo, const float* __restrict__ Vo, const float* __restrict__ bo,
                       float* __restrict__ out, long long out_size)
{
    // warp-private h stage, double buffered: [buf][batch][col]
    __shared__ __align__(16) float hs[2][2][HPF];

    const int lane = threadIdx.x;
    const int j    = blockIdx.x % NBLK;       // hidden block 0..19
    const int grp  = blockIdx.x / NBLK;       // 0..63
    const int b0   = grp * 2;
    const int col  = j * HPF + lane;

    const float* Vg[4] = {Vi, Vf, Vc, Vo};
    const float* Ug[4] = {Ui, Uf, Uc, Uo};
    const float* Bg[4] = {bi, bf, bc, bo};

    // ---- all 4 gate V-blocks -> registers, packed over m-pairs ----
    // vr[g][q] = ( V_g[2q][col], V_g[2q+1][col] )
    unsigned long long vr[4][16];
    #pragma unroll
    for (int g = 0; g < 4; ++g) {
        #pragma unroll
        for (int q = 0; q < 16; ++q) {
            const float v0 = __ldg(&Vg[g][(j * HPF + 2 * q)     * HID + col]);
            const float v1 = __ldg(&Vg[g][(j * HPF + 2 * q + 1) * HID + col]);
            vr[g][q] = pk2(v0, v1);
        }
    }

    // ---- bias + folded masked-U input projection ----
    float ua[4], ub[4], bias[4];
    #pragma unroll
    for (int g = 0; g < 4; ++g) {
        float a = 0.0f, bb = 0.0f;
        if (j < 16) a = __ldg(&Ug[g][j * HID + col]);
        if (j == 0) { a += __ldg(&Ug[g][16 * HID + col]); bb = __ldg(&Ug[g][17 * HID + col]); }
        if (j == 2) { a += __ldg(&Ug[g][18 * HID + col]); bb = __ldg(&Ug[g][19 * HID + col]); }
        ua[g] = a; ub[g] = bb;
        bias[g] = __ldg(&Bg[g][col]);
    }
    const int fa = (j == 0) ? 0 : ((j == 2) ? 2 : ((j < 16) ? j : 0));
    const int fb = (j == 0) ? 1 : ((j == 2) ? 3 : 0);   // ub==0 when unused

    const float* xq0 = x + (long long)(b0 + 0) * SEQ * INSZ;
    const float* xq1 = x + (long long)(b0 + 1) * SEQ * INSZ;
    float* outp0 = out + (long long)(b0 + 0) * SEQ * HID + col;
    float* outp1 = out + (long long)(b0 + 1) * SEQ * HID + col;

    float h0 = 0.0f, c0 = 0.0f, h1 = 0.0f, c1 = 0.0f;
    hs[0][0][lane] = 0.0f; hs[0][1][lane] = 0.0f;
    hs[1][0][lane] = 0.0f; hs[1][1][lane] = 0.0f;
    __syncwarp();

    // pipelined x: registers hold x(t) while x(t+1) loads during the matvec
    float xa0 = __ldg(xq0 + fa), xb0 = __ldg(xq0 + fb);
    float xa1 = __ldg(xq1 + fa), xb1 = __ldg(xq1 + fb);

    for (int t = 0; t < SEQ; ++t) {
        const float* rb = &hs[t & 1][0][0];          // holds h(t-1)
        float*       wb = &hs[(t + 1) & 1][0][0];    // will hold h(t)

        // issue next step's x loads (consumed at the *next* epilogue)
        const int tn = (t + 1 < SEQ) ? t + 1 : t;
        const float nxa0 = __ldg(xq0 + tn * INSZ + fa);
        const float nxb0 = __ldg(xq0 + tn * INSZ + fb);
        const float nxa1 = __ldg(xq1 + tn * INSZ + fa);
        const float nxb1 = __ldg(xq1 + tn * INSZ + fb);

        // per-gate constant term for this step (off the matvec critical path)
        float base0[4], base1[4];
        #pragma unroll
        for (int g = 0; g < 4; ++g) {
            base0[g] = fmaf(xa0, ua[g], fmaf(xb0, ub[g], bias[g]));
            base1[g] = fmaf(xa1, ua[g], fmaf(xb1, ub[g], bias[g]));
        }

        // split accumulators: even-q terms in A, odd-q terms in B (depth 8 each)
        unsigned long long accA[2][4], accB[2][4];
        #pragma unroll
        for (int g = 0; g < 4; ++g) {
            accA[0][g] = 0ull; accA[1][g] = 0ull;
            accB[0][g] = 0ull; accB[1][g] = 0ull;
        }

        #pragma unroll
        for (int q = 0; q < 8; ++q) {
            const ulonglong2 ha = *reinterpret_cast<const ulonglong2*>(rb + 4 * q);
            const ulonglong2 hb = *reinterpret_cast<const ulonglong2*>(rb + HPF + 4 * q);
            #pragma unroll
            for (int g = 0; g < 4; ++g) {
                fma2(accA[0][g], ha.x, vr[g][2 * q]);
                fma2(accA[1][g], hb.x, vr[g][2 * q]);
                fma2(accB[0][g], ha.y, vr[g][2 * q + 1]);
                fma2(accB[1][g], hb.y, vr[g][2 * q + 1]);
            }
        }

        // ---- epilogue batch 0 ----
        {
            const float2 pi = upk2(add2(accA[0][0], accB[0][0]));
            const float2 pf = upk2(add2(accA[0][1], accB[0][1]));
            const float2 pc = upk2(add2(accA[0][2], accB[0][2]));
            const float2 po = upk2(add2(accA[0][3], accB[0][3]));
            const float gi = pi.x + pi.y + base0[0];
            const float gf = pf.x + pf.y + base0[1];
            const float gg = pc.x + pc.y + base0[2];
            const float go = po.x + po.y + base0[3];
            const float it = fmaf(0.5f, tanhapx(0.5f * gi), 0.5f);
            const float ft = fmaf(0.5f, tanhapx(0.5f * gf), 0.5f);
            const float tg = tanhapx(gg);
            const float ot = fmaf(0.5f, tanhapx(0.5f * go), 0.5f);
            c0 = fmaf(ft, c0, it * tg);
            h0 = ot * tanhapx(c0);
            outp0[(long long)t * HID] = h0;
            wb[lane] = h0;
        }
        // ---- epilogue batch 1 ----
        {
            const float2 pi = upk2(add2(accA[1][0], accB[1][0]));
            const float2 pf = upk2(add2(accA[1][1], accB[1][1]));
            const float2 pc = upk2(add2(accA[1][2], accB[1][2]));
            const float2 po = upk2(add2(accA[1][3], accB[1][3]));
            const float gi = pi.x + pi.y + base1[0];
            const float gf = pf.x + pf.y + base1[1];
            const float gg = pc.x + pc.y + base1[2];
            const float go = po.x + po.y + base1[3];
            const float it = fmaf(0.5f, tanhapx(0.5f * gi), 0.5f);
            const float ft = fmaf(0.5f, tanhapx(0.5f * gf), 0.5f);
            const float tg = tanhapx(gg);
            const float ot = fmaf(0.5f, tanhapx(0.5f * go), 0.5f);
            c1 = fmaf(ft, c1, it * tg);
            h1 = ot * tanhapx(c1);
            outp1[(long long)t * HID] = h1;
            wb[HPF + lane] = h1;
        }

        xa0 = nxa0; xb0 = nxb0; xa1 = nxa1; xb1 = nxb1;
        __syncwarp();   // h(t) visible before next step's reads; also fences buffer reuse
    }

    // final (h_t, c_t) appended after hidden_seq when present in output buffer
    const long long hsz = (long long)BATCHN * SEQ * HID;
    if (out_size >= hsz + 2LL * BATCHN * HID) {
        out[hsz + (long long)(b0 + 0) * HID + col] = h0;
        out[hsz + (long long)(b0 + 1) * HID + col] = h1;
        out[hsz + (long long)BATCHN * HID + (long long)(b0 + 0) * HID + col] = c0;
        out[hsz + (long long)BATCHN * HID + (long long)(b0 + 1) * HID + col] = c1;
    }
}

extern "C" void kernel_launch(void* const* d_in, const int* in_sizes, int n_in,
                              void* d_out, int out_size)
{
    const float* x  = (const float*)d_in[0];
    const float* Ui = (const float*)d_in[1];
    const float* Vi = (const float*)d_in[2];
    const float* bi = (const float*)d_in[3];
    const float* Uf = (const float*)d_in[4];
    const float* Vf = (const float*)d_in[5];
    const float* bf = (const float*)d_in[6];
    const float* Uc = (const float*)d_in[7];
    const float* Vc = (const float*)d_in[8];
    const float* bc = (const float*)d_in[9];
    const float* Uo = (const float*)d_in[10];
    const float* Vo = (const float*)d_in[11];
    const float* bo = (const float*)d_in[12];
    float* out = (float*)d_out;

    lstm_fused_kernel<<<NCTA, 32>>>(
        x, Ui, Vi, bi, Uf, Vf, bf, Uc, Vc, bc, Uo, Vo, bo,
        out, (long long)out_size);
}

// round 8
// speedup vs baseline: 1.3194x; 1.3194x over previous
#include <cuda_runtime.h>

#define HPF 32
#define NBLK 20
#define HID 640
#define BATCHN 128
#define SEQ 512
#define INSZ 16
#define NCTA 1280          // 20 j-blocks * 64 batch-pairs (1 warp per CTA, NB=2)

// ---- packed fp32x2 helpers (sm_103a dual fp32) ----
__device__ __forceinline__ unsigned long long pk2(float a, float b) {
    unsigned long long r;
    asm("mov.b64 %0, {%1, %2};" : "=l"(r) : "f"(a), "f"(b));
    return r;
}
__device__ __forceinline__ float2 upk2(unsigned long long v) {
    float2 f;
    asm("mov.b64 {%0, %1}, %2;" : "=f"(f.x), "=f"(f.y) : "l"(v));
    return f;
}
__device__ __forceinline__ void fma2(unsigned long long& d,
                                     unsigned long long a, unsigned long long b) {
    asm("fma.rn.f32x2 %0, %1, %2, %0;" : "+l"(d) : "l"(a), "l"(b));
}
__device__ __forceinline__ float tanhapx(float x) {
    float r;
    asm("tanh.approx.f32 %0, %1;" : "=f"(r) : "f"(x));
    return r;
}

__global__ __launch_bounds__(32, 9)
void lstm_fused_kernel(const float* __restrict__ x,
                       const float* __restrict__ Ui, const float* __restrict__ Vi, const float* __restrict__ bi,
                       const float* __restrict__ Uf, const float* __restrict__ Vf, const float* __restrict__ bf,
                       const float* __restrict__ Uc, const float* __restrict__ Vc, const float* __restrict__ bc,
                       const float* __restrict__ Uo, const float* __restrict__ Vo, const float* __restrict__ bo,
                       float* __restrict__ out, long long out_size)
{
    // warp-private h stage, double buffered: [buf][batch][col]
    __shared__ __align__(16) float hs[2][2][HPF];
    // staged x features: xs[batch][t] = (x[.,t,fa], x[.,t,fb])  -- 8KB
    __shared__ __align__(16) float2 xs[2][SEQ];

    const int lane = threadIdx.x;
    const int j    = blockIdx.x % NBLK;       // hidden block 0..19
    const int grp  = blockIdx.x / NBLK;       // 0..63
    const int b0   = grp * 2;
    const int col  = j * HPF + lane;

    const float* Vg[4] = {Vi, Vf, Vc, Vo};
    const float* Ug[4] = {Ui, Uf, Uc, Uo};
    const float* Bg[4] = {bi, bf, bc, bo};

    // ---- all 4 gate V-blocks -> registers, packed over m-pairs ----
    // vr[g][q] = ( V_g[2q][col], V_g[2q+1][col] )
    unsigned long long vr[4][16];
    #pragma unroll
    for (int g = 0; g < 4; ++g) {
        #pragma unroll
        for (int q = 0; q < 16; ++q) {
            const float v0 = __ldg(&Vg[g][(j * HPF + 2 * q)     * HID + col]);
            const float v1 = __ldg(&Vg[g][(j * HPF + 2 * q + 1) * HID + col]);
            vr[g][q] = pk2(v0, v1);
        }
    }

    // ---- bias + folded masked-U input projection ----
    float ua[4], ub[4], bias[4];
    #pragma unroll
    for (int g = 0; g < 4; ++g) {
        float a = 0.0f, bb = 0.0f;
        if (j < 16) a = __ldg(&Ug[g][j * HID + col]);
        if (j == 0) { a += __ldg(&Ug[g][16 * HID + col]); bb = __ldg(&Ug[g][17 * HID + col]); }
        if (j == 2) { a += __ldg(&Ug[g][18 * HID + col]); bb = __ldg(&Ug[g][19 * HID + col]); }
        ua[g] = a; ub[g] = bb;
        bias[g] = __ldg(&Bg[g][col]);
    }
    const int fa = (j == 0) ? 0 : ((j == 2) ? 2 : ((j < 16) ? j : 0));
    const int fb = (j == 0) ? 1 : ((j == 2) ? 3 : 0);   // ub==0 when unused

    const float* xq0 = x + (long long)(b0 + 0) * SEQ * INSZ;
    const float* xq1 = x + (long long)(b0 + 1) * SEQ * INSZ;
    float* outp0 = out + (long long)(b0 + 0) * SEQ * HID + col;
    float* outp1 = out + (long long)(b0 + 1) * SEQ * HID + col;

    // ---- one-time x gather into SMEM (removes all in-loop LDG) ----
    #pragma unroll 4
    for (int i = lane; i < SEQ; i += 32) {
        xs[0][i] = make_float2(__ldg(xq0 + i * INSZ + fa), __ldg(xq0 + i * INSZ + fb));
        xs[1][i] = make_float2(__ldg(xq1 + i * INSZ + fa), __ldg(xq1 + i * INSZ + fb));
    }

    float h0 = 0.0f, c0 = 0.0f, h1 = 0.0f, c1 = 0.0f;
    hs[0][0][lane] = 0.0f; hs[0][1][lane] = 0.0f;
    hs[1][0][lane] = 0.0f; hs[1][1][lane] = 0.0f;
    __syncwarp();

    for (int t = 0; t < SEQ; ++t) {
        const float* rb = &hs[t & 1][0][0];          // holds h(t-1)
        float*       wb = &hs[(t + 1) & 1][0][0];    // will hold h(t)

        // broadcast LDS, issued well before epilogue consumption
        const float2 x0 = xs[0][t];
        const float2 x1 = xs[1][t];

        unsigned long long acc[2][4];
        #pragma unroll
        for (int g = 0; g < 4; ++g) { acc[0][g] = 0ull; acc[1][g] = 0ull; }

        #pragma unroll
        for (int q = 0; q < 8; ++q) {
            const ulonglong2 ha = *reinterpret_cast<const ulonglong2*>(rb + 4 * q);
            const ulonglong2 hb = *reinterpret_cast<const ulonglong2*>(rb + HPF + 4 * q);
            #pragma unroll
            for (int g = 0; g < 4; ++g) {
                fma2(acc[0][g], ha.x, vr[g][2 * q]);
                fma2(acc[1][g], hb.x, vr[g][2 * q]);
                fma2(acc[0][g], ha.y, vr[g][2 * q + 1]);
                fma2(acc[1][g], hb.y, vr[g][2 * q + 1]);
            }
        }

        // ---- epilogue batch 0 ----
        {
            const float2 pi = upk2(acc[0][0]);
            const float2 pf = upk2(acc[0][1]);
            const float2 pc = upk2(acc[0][2]);
            const float2 po = upk2(acc[0][3]);
            const float gi = pi.x + pi.y + fmaf(x0.x, ua[0], fmaf(x0.y, ub[0], bias[0]));
            const float gf = pf.x + pf.y + fmaf(x0.x, ua[1], fmaf(x0.y, ub[1], bias[1]));
            const float gg = pc.x + pc.y + fmaf(x0.x, ua[2], fmaf(x0.y, ub[2], bias[2]));
            const float go = po.x + po.y + fmaf(x0.x, ua[3], fmaf(x0.y, ub[3], bias[3]));
            const float it = fmaf(0.5f, tanhapx(0.5f * gi), 0.5f);
            const float ft = fmaf(0.5f, tanhapx(0.5f * gf), 0.5f);
            const float tg = tanhapx(gg);
            const float ot = fmaf(0.5f, tanhapx(0.5f * go), 0.5f);
            c0 = fmaf(ft, c0, it * tg);
            h0 = ot * tanhapx(c0);
            outp0[(long long)t * HID] = h0;
            wb[lane] = h0;
        }
        // ---- epilogue batch 1 ----
        {
            const float2 pi = upk2(acc[1][0]);
            const float2 pf = upk2(acc[1][1]);
            const float2 pc = upk2(acc[1][2]);
            const float2 po = upk2(acc[1][3]);
            const float gi = pi.x + pi.y + fmaf(x1.x, ua[0], fmaf(x1.y, ub[0], bias[0]));
            const float gf = pf.x + pf.y + fmaf(x1.x, ua[1], fmaf(x1.y, ub[1], bias[1]));
            const float gg = pc.x + pc.y + fmaf(x1.x, ua[2], fmaf(x1.y, ub[2], bias[2]));
            const float go = po.x + po.y + fmaf(x1.x, ua[3], fmaf(x1.y, ub[3], bias[3]));
            const float it = fmaf(0.5f, tanhapx(0.5f * gi), 0.5f);
            const float ft = fmaf(0.5f, tanhapx(0.5f * gf), 0.5f);
            const float tg = tanhapx(gg);
            const float ot = fmaf(0.5f, tanhapx(0.5f * go), 0.5f);
            c1 = fmaf(ft, c1, it * tg);
            h1 = ot * tanhapx(c1);
            outp1[(long long)t * HID] = h1;
            wb[HPF + lane] = h1;
        }
        __syncwarp();   // h(t) visible before next step's reads
    }

    // final (h_t, c_t) appended after hidden_seq when present in output buffer
    const long long hsz = (long long)BATCHN * SEQ * HID;
    if (out_size >= hsz + 2LL * BATCHN * HID) {
        out[hsz + (long long)(b0 + 0) * HID + col] = h0;
        out[hsz + (long long)(b0 + 1) * HID + col] = h1;
        out[hsz + (long long)BATCHN * HID + (long long)(b0 + 0) * HID + col] = c0;
        out[hsz + (long long)BATCHN * HID + (long long)(b0 + 1) * HID + col] = c1;
    }
}

extern "C" void kernel_launch(void* const* d_in, const int* in_sizes, int n_in,
                              void* d_out, int out_size)
{
    const float* x  = (const float*)d_in[0];
    const float* Ui = (const float*)d_in[1];
    const float* Vi = (const float*)d_in[2];
    const float* bi = (const float*)d_in[3];
    const float* Uf = (const float*)d_in[4];
    const float* Vf = (const float*)d_in[5];
    const float* bf = (const float*)d_in[6];
    const float* Uc = (const float*)d_in[7];
    const float* Vc = (const float*)d_in[8];
    const float* bc = (const float*)d_in[9];
    const float* Uo = (const float*)d_in[10];
    const float* Vo = (const float*)d_in[11];
    const float* bo = (const float*)d_in[12];
    float* out = (float*)d_out;

    lstm_fused_kernel<<<NCTA, 32>>>(
        x, Ui, Vi, bi, Uf, Vf, bf, Uc, Vc, bc, Uo, Vo, bo,
        out, (long long)out_size);
}

// round 9
// speedup vs baseline: 1.3707x; 1.0389x over previous
#include <cuda_runtime.h>

#define HPF 32
#define NBLK 20
#define HID 640
#define BATCHN 128
#define SEQ 512
#define INSZ 16
#define NCTA 1280          // 20 j-blocks * 64 batch-pairs (1 warp per CTA, NB=2)

// ---- packed fp32x2 helpers (sm_103a dual fp32) ----
__device__ __forceinline__ unsigned long long pk2(float a, float b) {
    unsigned long long r;
    asm("mov.b64 %0, {%1, %2};" : "=l"(r) : "f"(a), "f"(b));
    return r;
}
__device__ __forceinline__ float2 upk2(unsigned long long v) {
    float2 f;
    asm("mov.b64 {%0, %1}, %2;" : "=f"(f.x), "=f"(f.y) : "l"(v));
    return f;
}
__device__ __forceinline__ void fma2(unsigned long long& d,
                                     unsigned long long a, unsigned long long b) {
    asm("fma.rn.f32x2 %0, %1, %2, %0;" : "+l"(d) : "l"(a), "l"(b));
}
__device__ __forceinline__ float tanhapx(float x) {
    float r;
    asm("tanh.approx.f32 %0, %1;" : "=f"(r) : "f"(x));
    return r;
}

__global__ __launch_bounds__(32, 9)
void lstm_fused_kernel(const float* __restrict__ x,
                       const float* __restrict__ Ui, const float* __restrict__ Vi, const float* __restrict__ bi,
                       const float* __restrict__ Uf, const float* __restrict__ Vf, const float* __restrict__ bf,
                       const float* __restrict__ Uc, const float* __restrict__ Vc, const float* __restrict__ bc,
                       const float* __restrict__ Uo, const float* __restrict__ Vo, const float* __restrict__ bo,
                       float* __restrict__ out, long long out_size)
{
    // per-batch h stages (single buffer each: write/read alternate across syncs)
    __shared__ __align__(16) float hs0[HPF];
    __shared__ __align__(16) float hs1[HPF];
    // staged x features (+1 pad entry read by the final, discarded phase B)
    __shared__ __align__(16) float2 xs[2][SEQ + 1];

    const int lane = threadIdx.x;
    const int j    = blockIdx.x % NBLK;       // hidden block 0..19
    const int grp  = blockIdx.x / NBLK;       // 0..63
    const int b0   = grp * 2;
    const int col  = j * HPF + lane;

    const float* Vg[4] = {Vi, Vf, Vc, Vo};
    const float* Ug[4] = {Ui, Uf, Uc, Uo};
    const float* Bg[4] = {bi, bf, bc, bo};

    // ---- all 4 gate V-blocks -> registers, packed over m-pairs ----
    unsigned long long vr[4][16];
    #pragma unroll
    for (int g = 0; g < 4; ++g) {
        #pragma unroll
        for (int q = 0; q < 16; ++q) {
            const float v0 = __ldg(&Vg[g][(j * HPF + 2 * q)     * HID + col]);
            const float v1 = __ldg(&Vg[g][(j * HPF + 2 * q + 1) * HID + col]);
            vr[g][q] = pk2(v0, v1);
        }
    }

    // ---- bias + folded masked-U input projection ----
    float ua[4], ub[4], bias[4];
    #pragma unroll
    for (int g = 0; g < 4; ++g) {
        float a = 0.0f, bb = 0.0f;
        if (j < 16) a = __ldg(&Ug[g][j * HID + col]);
        if (j == 0) { a += __ldg(&Ug[g][16 * HID + col]); bb = __ldg(&Ug[g][17 * HID + col]); }
        if (j == 2) { a += __ldg(&Ug[g][18 * HID + col]); bb = __ldg(&Ug[g][19 * HID + col]); }
        ua[g] = a; ub[g] = bb;
        bias[g] = __ldg(&Bg[g][col]);
    }
    const int fa = (j == 0) ? 0 : ((j == 2) ? 2 : ((j < 16) ? j : 0));
    const int fb = (j == 0) ? 1 : ((j == 2) ? 3 : 0);   // ub==0 when unused

    const float* xq0 = x + (long long)(b0 + 0) * SEQ * INSZ;
    const float* xq1 = x + (long long)(b0 + 1) * SEQ * INSZ;
    float* outp0 = out + (long long)(b0 + 0) * SEQ * HID + col;
    float* outp1 = out + (long long)(b0 + 1) * SEQ * HID + col;

    // ---- one-time x gather into SMEM ----
    #pragma unroll 4
    for (int i = lane; i < SEQ; i += 32) {
        xs[0][i] = make_float2(__ldg(xq0 + i * INSZ + fa), __ldg(xq0 + i * INSZ + fb));
        xs[1][i] = make_float2(__ldg(xq1 + i * INSZ + fa), __ldg(xq1 + i * INSZ + fb));
    }
    if (lane == 0) { xs[0][SEQ] = make_float2(0.f, 0.f); xs[1][SEQ] = make_float2(0.f, 0.f); }

    float h0 = 0.0f, c0 = 0.0f, h1 = 0.0f, c1 = 0.0f;
    hs0[lane] = 0.0f; hs1[lane] = 0.0f;
    __syncwarp();

    // prologue: acc0 for t=0 (h0(-1)=0 -> matvec contributes nothing, only base)
    unsigned long long acc0[4];
    {
        const float2 x0 = xs[0][0];
        #pragma unroll
        for (int g = 0; g < 4; ++g)
            acc0[g] = pk2(fmaf(x0.x, ua[g], fmaf(x0.y, ub[g], bias[g])), 0.0f);
    }

    for (int t = 0; t < SEQ; ++t) {
        // ================= Phase A: matvec1(t)  ||  epilogue0(t) =================
        unsigned long long acc1[4];
        {
            const float2 x1 = xs[1][t];
            #pragma unroll
            for (int g = 0; g < 4; ++g)
                acc1[g] = pk2(fmaf(x1.x, ua[g], fmaf(x1.y, ub[g], bias[g])), 0.0f);
        }
        #pragma unroll
        for (int q = 0; q < 8; ++q) {
            const ulonglong2 hb = *reinterpret_cast<const ulonglong2*>(hs1 + 4 * q);
            #pragma unroll
            for (int g = 0; g < 4; ++g) {
                fma2(acc1[g], hb.x, vr[g][2 * q]);
                fma2(acc1[g], hb.y, vr[g][2 * q + 1]);
            }
        }
        // epilogue batch 0 (uses acc0 from previous phase B / prologue)
        {
            const float2 pi = upk2(acc0[0]);
            const float2 pf = upk2(acc0[1]);
            const float2 pc = upk2(acc0[2]);
            const float2 po = upk2(acc0[3]);
            const float it = fmaf(0.5f, tanhapx(0.5f * (pi.x + pi.y)), 0.5f);
            const float ft = fmaf(0.5f, tanhapx(0.5f * (pf.x + pf.y)), 0.5f);
            const float tg = tanhapx(pc.x + pc.y);
            const float ot = fmaf(0.5f, tanhapx(0.5f * (po.x + po.y)), 0.5f);
            c0 = fmaf(ft, c0, it * tg);
            h0 = ot * tanhapx(c0);
            outp0[(long long)t * HID] = h0;
            hs0[lane] = h0;
        }
        __syncwarp();

        // ================= Phase B: matvec0(t+1)  ||  epilogue1(t) ================
        {
            const float2 x0 = xs[0][t + 1];
            #pragma unroll
            for (int g = 0; g < 4; ++g)
                acc0[g] = pk2(fmaf(x0.x, ua[g], fmaf(x0.y, ub[g], bias[g])), 0.0f);
        }
        #pragma unroll
        for (int q = 0; q < 8; ++q) {
            const ulonglong2 ha = *reinterpret_cast<const ulonglong2*>(hs0 + 4 * q);
            #pragma unroll
            for (int g = 0; g < 4; ++g) {
                fma2(acc0[g], ha.x, vr[g][2 * q]);
                fma2(acc0[g], ha.y, vr[g][2 * q + 1]);
            }
        }
        // epilogue batch 1 (uses acc1 from phase A)
        {
            const float2 pi = upk2(acc1[0]);
            const float2 pf = upk2(acc1[1]);
            const float2 pc = upk2(acc1[2]);
            const float2 po = upk2(acc1[3]);
            const float it = fmaf(0.5f, tanhapx(0.5f * (pi.x + pi.y)), 0.5f);
            const float ft = fmaf(0.5f, tanhapx(0.5f * (pf.x + pf.y)), 0.5f);
            const float tg = tanhapx(pc.x + pc.y);
            const float ot = fmaf(0.5f, tanhapx(0.5f * (po.x + po.y)), 0.5f);
            c1 = fmaf(ft, c1, it * tg);
            h1 = ot * tanhapx(c1);
            outp1[(long long)t * HID] = h1;
            hs1[lane] = h1;
        }
        __syncwarp();
    }

    // final (h_t, c_t) appended after hidden_seq when present in output buffer
    const long long hsz = (long long)BATCHN * SEQ * HID;
    if (out_size >= hsz + 2LL * BATCHN * HID) {
        out[hsz + (long long)(b0 + 0) * HID + col] = h0;
        out[hsz + (long long)(b0 + 1) * HID + col] = h1;
        out[hsz + (long long)BATCHN * HID + (long long)(b0 + 0) * HID + col] = c0;
        out[hsz + (long long)BATCHN * HID + (long long)(b0 + 1) * HID + col] = c1;
    }
}

extern "C" void kernel_launch(void* const* d_in, const int* in_sizes, int n_in,
                              void* d_out, int out_size)
{
    const float* x  = (const float*)d_in[0];
    const float* Ui = (const float*)d_in[1];
    const float* Vi = (const float*)d_in[2];
    const float* bi = (const float*)d_in[3];
    const float* Uf = (const float*)d_in[4];
    const float* Vf = (const float*)d_in[5];
    const float* bf = (const float*)d_in[6];
    const float* Uc = (const float*)d_in[7];
    const float* Vc = (const float*)d_in[8];
    const float* bc = (const float*)d_in[9];
    const float* Uo = (const float*)d_in[10];
    const float* Vo = (const float*)d_in[11];
    const float* bo = (const float*)d_in[12];
    float* out = (float*)d_out;

    lstm_fused_kernel<<<NCTA, 32>>>(
        x, Ui, Vi, bi, Uf, Vf, bf, Uc, Vc, bc, Uo, Vo, bo,
        out, (long long)out_size);
}